// round 12
// baseline (speedup 1.0000x reference)
#include <cuda_runtime.h>
#include <cstdint>
#include <cstddef>

#define TT 1024
#define II 64
#define HH 128
#define NCTA 128

typedef unsigned long long u64;

// ---- loop-kernel smem layout (bytes) ----
// weights: [11 slots][4 kq][256 colidx] x 16B ; slot stride = 4*256*16 = 16384
#define OFF_WS  0
#define OFF_GS  180224   // float [4 kq][4 r][512 col] partial gate sums (32 KB)
#define OFF_H   212992   // float [4][128] hidden state
#define OFF_WEF 215040   // float [128]
#define OFF_BE  215552   // float [4]
#define SMEM_BYTES 215568

// xp scratch: [b][t][g] fp32 (+pad so the s+1 prefetch at the last step is safe)
__device__ float g_xp[(size_t)512 * TT * 512 + 1024];

__device__ __forceinline__ u64 fma2(u64 a, u64 b, u64 c) {
    u64 d;
    asm("fma.rn.f32x2 %0, %1, %2, %3;" : "=l"(d) : "l"(a), "l"(b), "l"(c));
    return d;
}
__device__ __forceinline__ void lds_v2(uint32_t a, u64& v0, u64& v1) {
    asm volatile("ld.shared.v2.u64 {%0,%1}, [%2];" : "=l"(v0), "=l"(v1) : "r"(a));
}
__device__ __forceinline__ float2 unpack2(u64 v) {
    float2 r;
    asm("mov.b64 {%0,%1}, %2;" : "=f"(r.x), "=f"(r.y) : "l"(v));
    return r;
}
__device__ __forceinline__ float sigmoid_f(float x) {
    return __fdividef(1.0f, 1.0f + __expf(-x));
}
__device__ __forceinline__ float tanh_f(float x) {
    return __fdividef(2.0f, 1.0f + __expf(-2.0f * x)) - 1.0f;
}

// ================= prologue: xp[b][s][g] = x[b][s][:] . W_ih[g][:] =================
// grid 4096: bb = bx & 127 (4 batch rows), sbk = bx >> 7 (32 timesteps). 512 threads = gate g.
// 4 timestep-outputs in flight x 2 k-chains each = 8 independent FMA chains per thread.
__global__ void __launch_bounds__(512, 1)
xproj_kernel(const float* __restrict__ x, const float* __restrict__ W_ih)
{
    __shared__ float xt[4 * 32 * II];   // 32 KB
    const int t   = threadIdx.x;
    const int bb  = blockIdx.x & 127;
    const int sbk = blockIdx.x >> 7;

    // stage x tile: 4 rows x (32 steps * 64) contiguous floats each
    #pragma unroll
    for (int i = 0; i < 4; ++i) {
        const float4* src = reinterpret_cast<const float4*>(
            x + ((size_t)(bb * 4 + i) * TT + sbk * 32) * II);
        reinterpret_cast<float4*>(xt)[i * 512 + t] = src[t];
    }

    u64 w[32];
    {
        const u64* p = reinterpret_cast<const u64*>(W_ih + t * II);
        #pragma unroll
        for (int q = 0; q < 32; ++q) w[q] = p[q];
    }
    __syncthreads();

    const uint32_t sx = (uint32_t)__cvta_generic_to_shared(xt);
    #pragma unroll 1
    for (int i = 0; i < 4; ++i) {
        float* dst = &g_xp[((size_t)(bb * 4 + i) * TT + sbk * 32) * 512 + t];
        #pragma unroll 1
        for (int sg = 0; sg < 8; ++sg) {
            // 4 timesteps s = sg*4 .. sg*4+3 ; x rows at 256B stride
            const uint32_t ba = sx + i * 8192 + sg * 1024;
            u64 A0 = 0ull, A1 = 0ull, A2 = 0ull, A3 = 0ull;   // low-k chains
            u64 B0 = 0ull, B1 = 0ull, B2 = 0ull, B3 = 0ull;   // high-k chains
            #pragma unroll
            for (int q = 0; q < 8; ++q) {
                u64 la, lb;
                lds_v2(ba + 0 * 256 + q * 16, la, lb);
                A0 = fma2(w[2 * q], la, A0);  A0 = fma2(w[2 * q + 1], lb, A0);
                lds_v2(ba + 1 * 256 + q * 16, la, lb);
                A1 = fma2(w[2 * q], la, A1);  A1 = fma2(w[2 * q + 1], lb, A1);
                lds_v2(ba + 2 * 256 + q * 16, la, lb);
                A2 = fma2(w[2 * q], la, A2);  A2 = fma2(w[2 * q + 1], lb, A2);
                lds_v2(ba + 3 * 256 + q * 16, la, lb);
                A3 = fma2(w[2 * q], la, A3);  A3 = fma2(w[2 * q + 1], lb, A3);

                lds_v2(ba + 0 * 256 + 128 + q * 16, la, lb);
                B0 = fma2(w[16 + 2 * q], la, B0);  B0 = fma2(w[16 + 2 * q + 1], lb, B0);
                lds_v2(ba + 1 * 256 + 128 + q * 16, la, lb);
                B1 = fma2(w[16 + 2 * q], la, B1);  B1 = fma2(w[16 + 2 * q + 1], lb, B1);
                lds_v2(ba + 2 * 256 + 128 + q * 16, la, lb);
                B2 = fma2(w[16 + 2 * q], la, B2);  B2 = fma2(w[16 + 2 * q + 1], lb, B2);
                lds_v2(ba + 3 * 256 + 128 + q * 16, la, lb);
                B3 = fma2(w[16 + 2 * q], la, B3);  B3 = fma2(w[16 + 2 * q + 1], lb, B3);
            }
            float2 fa, fb;
            fa = unpack2(A0); fb = unpack2(B0);
            dst[(size_t)(sg * 4 + 0) * 512] = (fa.x + fa.y) + (fb.x + fb.y);
            fa = unpack2(A1); fb = unpack2(B1);
            dst[(size_t)(sg * 4 + 1) * 512] = (fa.x + fa.y) + (fb.x + fb.y);
            fa = unpack2(A2); fb = unpack2(B2);
            dst[(size_t)(sg * 4 + 2) * 512] = (fa.x + fa.y) + (fb.x + fb.y);
            fa = unpack2(A3); fb = unpack2(B3);
            dst[(size_t)(sg * 4 + 3) * 512] = (fa.x + fa.y) + (fb.x + fb.y);
        }
    }
}

// ================= sequential LSTM loop: 128 CTAs x 1024 threads =================
// thread: colidx = t&255 -> gate columns (colidx, colidx+256); kq = t>>8 -> k in [32kq, 32kq+32)
__global__ void __launch_bounds__(1024, 1)
lstm_loop_kernel(const float* __restrict__ W_hh,
                 const float* __restrict__ b_ih, const float* __restrict__ b_hh,
                 const float* __restrict__ W1, const float* __restrict__ b1,
                 const float* __restrict__ W2, const float* __restrict__ b2,
                 float* __restrict__ out)
{
    extern __shared__ char smem[];
    const int t      = threadIdx.x;
    const int colidx = t & 255;
    const int kq     = t >> 8;
    const int kb     = kq * 32;
    const int c0     = colidx;
    const int c1     = colidx + 256;
    const int r0     = blockIdx.x * 4;
    const uint32_t sb = (uint32_t)__cvta_generic_to_shared(smem);

    // register weights: W_hh[c0][kb .. kb+19] as 10 u64 pairs
    u64 wA[10];
    {
        const u64* p = reinterpret_cast<const u64*>(W_hh + c0 * HH + kb);
        #pragma unroll
        for (int q = 0; q < 10; ++q) wA[q] = p[q];
    }

    // smem weights: slots 0..2 = c0 k kb+20..kb+31 ; slots 3..10 = c1 k kb..kb+31
    {
        const float4* pa = reinterpret_cast<const float4*>(W_hh + c0 * HH + kb + 20);
        #pragma unroll
        for (int s2 = 0; s2 < 3; ++s2)
            *reinterpret_cast<float4*>(smem + OFF_WS + ((s2 * 4 + kq) * 256 + colidx) * 16) = pa[s2];
        const float4* pb = reinterpret_cast<const float4*>(W_hh + c1 * HH + kb);
        #pragma unroll
        for (int s2 = 0; s2 < 8; ++s2)
            *reinterpret_cast<float4*>(smem + OFF_WS + (((s2 + 3) * 4 + kq) * 256 + colidx) * 16) = pb[s2];
    }

    float* gs   = reinterpret_cast<float*>(smem + OFF_GS);
    float* hs   = reinterpret_cast<float*>(smem + OFF_H);
    float* weff = reinterpret_cast<float*>(smem + OFF_WEF);
    float* beff = reinterpret_cast<float*>(smem + OFF_BE);

    if (t < 512) hs[t] = 0.0f;
    if (t >= 512 && t < 640) {
        float s = 0.0f;
        for (int m = 0; m < 256; ++m) s += W2[m] * W1[m * HH + (t - 512)];
        weff[t - 512] = s;
    }
    if (t == 640) {
        float s = b2[0];
        for (int m = 0; m < 256; ++m) s += W2[m] * b1[m];
        beff[0] = s;
    }

    // ---- phase-B per-thread state (threads 0..511): row br, h-column bj ----
    const int br = (t >> 7) & 3;
    const int bj = t & 127;
    float biasI = 0.f, biasF = 0.f, biasG = 0.f, biasO = 0.f;
    const float* xpp = g_xp + ((size_t)(r0 + br) * TT) * 512 + bj;
    float xv0 = 0.f, xv1 = 0.f, xv2 = 0.f, xv3 = 0.f;
    float cval = 0.0f;
    if (t < 512) {
        biasI = b_ih[bj]            + b_hh[bj];
        biasF = b_ih[HH + bj]       + b_hh[HH + bj];
        biasG = b_ih[2 * HH + bj]   + b_hh[2 * HH + bj];
        biasO = b_ih[3 * HH + bj]   + b_hh[3 * HH + bj];
        xv0 = __ldg(xpp);
        xv1 = __ldg(xpp + 128);
        xv2 = __ldg(xpp + 256);
        xv3 = __ldg(xpp + 384);
    }

    const uint32_t aW = sb + OFF_WS + (kq * 256 + colidx) * 16;
    const uint32_t aH = sb + OFF_H + kb * 4;

    __syncthreads();

    #pragma unroll 1
    for (int s = 0; s < TT; ++s) {
        // ---------------- phase A: partial gate sums over this thread's 32 k ----------------
        u64 a0r0 = 0ull, a0r1 = 0ull, a0r2 = 0ull, a0r3 = 0ull;
        u64 a1r0 = 0ull, a1r1 = 0ull, a1r2 = 0ull, a1r3 = 0ull;

        #pragma unroll
        for (int g = 0; g < 8; ++g) {
            u64 wb0, wb1;
            lds_v2(aW + (3 + g) * 16384, wb0, wb1);        // c1 weights
            u64 wa0, wa1;
            if (g < 5) { wa0 = wA[2 * g]; wa1 = wA[2 * g + 1]; }
            else       { lds_v2(aW + (g - 5) * 16384, wa0, wa1); }

            u64 p0, p1;
            lds_v2(aH + 0 * 512 + g * 16, p0, p1);
            a0r0 = fma2(wa0, p0, a0r0);  a0r0 = fma2(wa1, p1, a0r0);
            a1r0 = fma2(wb0, p0, a1r0);  a1r0 = fma2(wb1, p1, a1r0);
            lds_v2(aH + 1 * 512 + g * 16, p0, p1);
            a0r1 = fma2(wa0, p0, a0r1);  a0r1 = fma2(wa1, p1, a0r1);
            a1r1 = fma2(wb0, p0, a1r1);  a1r1 = fma2(wb1, p1, a1r1);
            lds_v2(aH + 2 * 512 + g * 16, p0, p1);
            a0r2 = fma2(wa0, p0, a0r2);  a0r2 = fma2(wa1, p1, a0r2);
            a1r2 = fma2(wb0, p0, a1r2);  a1r2 = fma2(wb1, p1, a1r2);
            lds_v2(aH + 3 * 512 + g * 16, p0, p1);
            a0r3 = fma2(wa0, p0, a0r3);  a0r3 = fma2(wa1, p1, a0r3);
            a1r3 = fma2(wb0, p0, a1r3);  a1r3 = fma2(wb1, p1, a1r3);
        }

        {
            float2 f;
            f = unpack2(a0r0); gs[(kq * 4 + 0) * 512 + c0] = f.x + f.y;
            f = unpack2(a0r1); gs[(kq * 4 + 1) * 512 + c0] = f.x + f.y;
            f = unpack2(a0r2); gs[(kq * 4 + 2) * 512 + c0] = f.x + f.y;
            f = unpack2(a0r3); gs[(kq * 4 + 3) * 512 + c0] = f.x + f.y;
            f = unpack2(a1r0); gs[(kq * 4 + 0) * 512 + c1] = f.x + f.y;
            f = unpack2(a1r1); gs[(kq * 4 + 1) * 512 + c1] = f.x + f.y;
            f = unpack2(a1r2); gs[(kq * 4 + 2) * 512 + c1] = f.x + f.y;
            f = unpack2(a1r3); gs[(kq * 4 + 3) * 512 + c1] = f.x + f.y;
        }
        __syncthreads();

        // ---------------- phase B: reduce partials, activations, state update ----------------
        if (t < 512) {
            // prefetch xp for step s+1 (pad in g_xp covers the final step)
            const float* xn = xpp + (size_t)(s + 1) * 512;
            float xn0 = __ldg(xn), xn1 = __ldg(xn + 128), xn2 = __ldg(xn + 256), xn3 = __ldg(xn + 384);

            float pi = xv0 + biasI, pf = xv1 + biasF, pg = xv2 + biasG, po = xv3 + biasO;
            #pragma unroll
            for (int q = 0; q < 4; ++q) {
                const int base = (q * 4 + br) * 512 + bj;
                pi += gs[base];
                pf += gs[base + 128];
                pg += gs[base + 256];
                po += gs[base + 384];
            }
            float ig = sigmoid_f(pi);
            float fg = sigmoid_f(pf);
            float gv = tanh_f(pg);
            float og = sigmoid_f(po);
            cval = fg * cval + ig * gv;
            hs[br * HH + bj] = og * tanh_f(cval);
            xv0 = xn0; xv1 = xn1; xv2 = xn2; xv3 = xn3;
        }
        __syncthreads();
    }

    // ---------------- fused fc1+fc2 epilogue ----------------
    if (t < 4) {
        float s = beff[0];
        #pragma unroll 8
        for (int j = 0; j < HH; ++j) s += hs[t * HH + j] * weff[j];
        out[r0 + t] = s;
    }
}

extern "C" void kernel_launch(void* const* d_in, const int* in_sizes, int n_in,
                              void* d_out, int out_size) {
    const float* x    = (const float*)d_in[0];
    const float* W_ih = (const float*)d_in[1];
    const float* W_hh = (const float*)d_in[2];
    const float* b_ih = (const float*)d_in[3];
    const float* b_hh = (const float*)d_in[4];
    const float* W1   = (const float*)d_in[5];
    const float* b1   = (const float*)d_in[6];
    const float* W2   = (const float*)d_in[7];
    const float* b2   = (const float*)d_in[8];
    float* out = (float*)d_out;

    cudaFuncSetAttribute(lstm_loop_kernel,
                         cudaFuncAttributeMaxDynamicSharedMemorySize, SMEM_BYTES);

    xproj_kernel<<<4096, 512>>>(x, W_ih);
    lstm_loop_kernel<<<NCTA, 1024, SMEM_BYTES>>>(W_hh, b_ih, b_hh, W1, b1, W2, b2, out);
}

// round 13
// speedup vs baseline: 1.1088x; 1.1088x over previous
#include <cuda_runtime.h>
#include <cstdint>
#include <cstddef>

#define TT 1024
#define II 64
#define HH 128
#define NCTA 128

typedef unsigned long long u64;

// ---- loop-kernel smem layout (bytes) ----
// weights: [11 slots][4 kq][256 colidx] x 16B ; slot stride = 4*256*16 = 16384
#define OFF_WS  0
#define OFF_GS  180224   // float [4 kq][4 r][512 col] partial gate sums (32 KB)
#define OFF_H   212992   // float [4][128] hidden state
#define OFF_WEF 215040   // float [128]
#define OFF_BE  215552   // float [4]
#define SMEM_BYTES 215568

// ---- xproj smem layout (floats) ----
#define XROW 260                  // padded words per k-row of xT (16B-aligned, 4-way stage conflicts)
#define WROW 516                  // padded words per k-row of wT
#define XP_SMEM_FLOATS (64 * XROW + 64 * WROW)
#define XP_SMEM_BYTES  (XP_SMEM_FLOATS * 4)   // 198656

// xp scratch: [b][t][g] fp32 (+pad so the s+1 prefetch at the last step is safe)
__device__ float g_xp[(size_t)512 * TT * 512 + 1024];

__device__ __forceinline__ u64 fma2(u64 a, u64 b, u64 c) {
    u64 d;
    asm("fma.rn.f32x2 %0, %1, %2, %3;" : "=l"(d) : "l"(a), "l"(b), "l"(c));
    return d;
}
__device__ __forceinline__ void lds_v2(uint32_t a, u64& v0, u64& v1) {
    asm volatile("ld.shared.v2.u64 {%0,%1}, [%2];" : "=l"(v0), "=l"(v1) : "r"(a));
}
__device__ __forceinline__ float2 unpack2(u64 v) {
    float2 r;
    asm("mov.b64 {%0,%1}, %2;" : "=f"(r.x), "=f"(r.y) : "l"(v));
    return r;
}
__device__ __forceinline__ u64 splat2(float v) {
    u64 r;
    asm("mov.b64 %0, {%1,%1};" : "=l"(r) : "f"(v));
    return r;
}
__device__ __forceinline__ float sigmoid_f(float x) {
    return __fdividef(1.0f, 1.0f + __expf(-x));
}
__device__ __forceinline__ float tanh_f(float x) {
    return __fdividef(2.0f, 1.0f + __expf(-2.0f * x)) - 1.0f;
}

// ================= prologue: xp[b][s][g] = x[b][s][:] . W_ih[g][:] =================
// Register-tiled SGEMM. Grid 4096: b = bx>>3, sblk = ((bx>>1)&3)*256, ghalf = (bx&1)*256.
// 512 threads; thread owns 8 s x 8 g per pass, 2 passes over the 256-s block.
// W pre-transposed in smem lane-major: per k, warp's 2 lds_v2 are contiguous 512B (4 wf each).
__global__ void __launch_bounds__(512, 1)
xproj_kernel(const float* __restrict__ x, const float* __restrict__ W_ih)
{
    extern __shared__ float sm[];
    const int t    = threadIdx.x;
    const int b    = blockIdx.x >> 3;
    const int sblk = ((blockIdx.x >> 1) & 3) * 256;
    const int gh   = (blockIdx.x & 1) * 256;

    float* xT = sm;               // [64][XROW]  xT[k][s_local]
    float* wT = sm + 64 * XROW;   // [64][WROW]  lane-major W for this g-half

    // ---- stage x: xT[k][s] = x[b][sblk+s][k]  (coalesced reads, 4-way write conflicts) ----
    {
        const int sl = t >> 6, k = t & 63;
        #pragma unroll
        for (int r = 0; r < 32; ++r)
            xT[k * XROW + r * 8 + sl] =
                x[((size_t)b * TT + sblk + r * 8 + sl) * II + k];
    }
    // ---- stage W (this g-half), lane-major: gl -> (u = gl>>3, half = (gl>>2)&1, j = gl&3) ----
    {
        const int gl0 = t >> 6, k = t & 63;
        #pragma unroll
        for (int r = 0; r < 32; ++r) {
            int gl = r * 8 + gl0;
            int u = gl >> 3, half = (gl >> 2) & 1, j = gl & 3;
            wT[k * WROW + half * 256 + u * 4 + j] = W_ih[(gh + gl) * II + k];
        }
    }
    __syncthreads();

    const int gg  = t & 31;    // g-group: owns g = gh + gg*8 .. +8
    const int sgp = t >> 5;    // s-group within pass: owns s = p*128 + sgp*8 .. +8
    const uint32_t sbase = (uint32_t)__cvta_generic_to_shared(sm);
    const uint32_t axb = sbase + (sgp * 8) * 4;
    const uint32_t awb = sbase + 64 * XROW * 4 + gg * 16;

    #pragma unroll 1
    for (int p = 0; p < 2; ++p) {
        u64 acc[32];
        #pragma unroll
        for (int q = 0; q < 32; ++q) acc[q] = 0ull;

        uint32_t ax = axb + p * 512;    // 128 s * 4B
        uint32_t aw = awb;

        #pragma unroll 4
        for (int k = 0; k < 64; ++k) {
            u64 xa, xb, xc, xd, w0, w1, w2, w3;
            lds_v2(ax, xa, xb);           // s..s+3   (broadcast, 1 wf each)
            lds_v2(ax + 16, xc, xd);      // s+4..s+7
            lds_v2(aw, w0, w1);           // g+0..3   (contiguous 512B/warp, 4 wf)
            lds_v2(aw + 1024, w2, w3);    // g+4..7
            ax += XROW * 4; aw += WROW * 4;

            float2 x01 = unpack2(xa), x23 = unpack2(xb);
            float2 x45 = unpack2(xc), x67 = unpack2(xd);
            u64 s0 = splat2(x01.x), s1 = splat2(x01.y);
            u64 s2 = splat2(x23.x), s3 = splat2(x23.y);
            u64 s4 = splat2(x45.x), s5 = splat2(x45.y);
            u64 s6 = splat2(x67.x), s7 = splat2(x67.y);

            acc[0]  = fma2(w0, s0, acc[0]);   acc[1]  = fma2(w1, s0, acc[1]);
            acc[2]  = fma2(w2, s0, acc[2]);   acc[3]  = fma2(w3, s0, acc[3]);
            acc[4]  = fma2(w0, s1, acc[4]);   acc[5]  = fma2(w1, s1, acc[5]);
            acc[6]  = fma2(w2, s1, acc[6]);   acc[7]  = fma2(w3, s1, acc[7]);
            acc[8]  = fma2(w0, s2, acc[8]);   acc[9]  = fma2(w1, s2, acc[9]);
            acc[10] = fma2(w2, s2, acc[10]);  acc[11] = fma2(w3, s2, acc[11]);
            acc[12] = fma2(w0, s3, acc[12]);  acc[13] = fma2(w1, s3, acc[13]);
            acc[14] = fma2(w2, s3, acc[14]);  acc[15] = fma2(w3, s3, acc[15]);
            acc[16] = fma2(w0, s4, acc[16]);  acc[17] = fma2(w1, s4, acc[17]);
            acc[18] = fma2(w2, s4, acc[18]);  acc[19] = fma2(w3, s4, acc[19]);
            acc[20] = fma2(w0, s5, acc[20]);  acc[21] = fma2(w1, s5, acc[21]);
            acc[22] = fma2(w2, s5, acc[22]);  acc[23] = fma2(w3, s5, acc[23]);
            acc[24] = fma2(w0, s6, acc[24]);  acc[25] = fma2(w1, s6, acc[25]);
            acc[26] = fma2(w2, s6, acc[26]);  acc[27] = fma2(w3, s6, acc[27]);
            acc[28] = fma2(w0, s7, acc[28]);  acc[29] = fma2(w1, s7, acc[29]);
            acc[30] = fma2(w2, s7, acc[30]);  acc[31] = fma2(w3, s7, acc[31]);
        }

        // store 8 s rows x 8 g contiguous floats (coalesced 1KB per warp per row)
        #pragma unroll
        for (int i = 0; i < 8; ++i) {
            size_t srow = (size_t)b * TT + sblk + p * 128 + sgp * 8 + i;
            float* dp = &g_xp[srow * 512 + gh + gg * 8];
            reinterpret_cast<ulonglong2*>(dp)[0] = make_ulonglong2(acc[i * 4 + 0], acc[i * 4 + 1]);
            reinterpret_cast<ulonglong2*>(dp)[1] = make_ulonglong2(acc[i * 4 + 2], acc[i * 4 + 3]);
        }
    }
}

// ================= sequential LSTM loop: 128 CTAs x 1024 threads (UNCHANGED) =================
__global__ void __launch_bounds__(1024, 1)
lstm_loop_kernel(const float* __restrict__ W_hh,
                 const float* __restrict__ b_ih, const float* __restrict__ b_hh,
                 const float* __restrict__ W1, const float* __restrict__ b1,
                 const float* __restrict__ W2, const float* __restrict__ b2,
                 float* __restrict__ out)
{
    extern __shared__ char smem[];
    const int t      = threadIdx.x;
    const int colidx = t & 255;
    const int kq     = t >> 8;
    const int kb     = kq * 32;
    const int c0     = colidx;
    const int c1     = colidx + 256;
    const int r0     = blockIdx.x * 4;
    const uint32_t sb = (uint32_t)__cvta_generic_to_shared(smem);

    u64 wA[10];
    {
        const u64* p = reinterpret_cast<const u64*>(W_hh + c0 * HH + kb);
        #pragma unroll
        for (int q = 0; q < 10; ++q) wA[q] = p[q];
    }

    {
        const float4* pa = reinterpret_cast<const float4*>(W_hh + c0 * HH + kb + 20);
        #pragma unroll
        for (int s2 = 0; s2 < 3; ++s2)
            *reinterpret_cast<float4*>(smem + OFF_WS + ((s2 * 4 + kq) * 256 + colidx) * 16) = pa[s2];
        const float4* pb = reinterpret_cast<const float4*>(W_hh + c1 * HH + kb);
        #pragma unroll
        for (int s2 = 0; s2 < 8; ++s2)
            *reinterpret_cast<float4*>(smem + OFF_WS + (((s2 + 3) * 4 + kq) * 256 + colidx) * 16) = pb[s2];
    }

    float* gs   = reinterpret_cast<float*>(smem + OFF_GS);
    float* hs   = reinterpret_cast<float*>(smem + OFF_H);
    float* weff = reinterpret_cast<float*>(smem + OFF_WEF);
    float* beff = reinterpret_cast<float*>(smem + OFF_BE);

    if (t < 512) hs[t] = 0.0f;
    if (t >= 512 && t < 640) {
        float s = 0.0f;
        for (int m = 0; m < 256; ++m) s += W2[m] * W1[m * HH + (t - 512)];
        weff[t - 512] = s;
    }
    if (t == 640) {
        float s = b2[0];
        for (int m = 0; m < 256; ++m) s += W2[m] * b1[m];
        beff[0] = s;
    }

    const int br = (t >> 7) & 3;
    const int bj = t & 127;
    float biasI = 0.f, biasF = 0.f, biasG = 0.f, biasO = 0.f;
    const float* xpp = g_xp + ((size_t)(r0 + br) * TT) * 512 + bj;
    float xv0 = 0.f, xv1 = 0.f, xv2 = 0.f, xv3 = 0.f;
    float cval = 0.0f;
    if (t < 512) {
        biasI = b_ih[bj]            + b_hh[bj];
        biasF = b_ih[HH + bj]       + b_hh[HH + bj];
        biasG = b_ih[2 * HH + bj]   + b_hh[2 * HH + bj];
        biasO = b_ih[3 * HH + bj]   + b_hh[3 * HH + bj];
        xv0 = __ldg(xpp);
        xv1 = __ldg(xpp + 128);
        xv2 = __ldg(xpp + 256);
        xv3 = __ldg(xpp + 384);
    }

    const uint32_t aW = sb + OFF_WS + (kq * 256 + colidx) * 16;
    const uint32_t aH = sb + OFF_H + kb * 4;

    __syncthreads();

    #pragma unroll 1
    for (int s = 0; s < TT; ++s) {
        u64 a0r0 = 0ull, a0r1 = 0ull, a0r2 = 0ull, a0r3 = 0ull;
        u64 a1r0 = 0ull, a1r1 = 0ull, a1r2 = 0ull, a1r3 = 0ull;

        #pragma unroll
        for (int g = 0; g < 8; ++g) {
            u64 wb0, wb1;
            lds_v2(aW + (3 + g) * 16384, wb0, wb1);
            u64 wa0, wa1;
            if (g < 5) { wa0 = wA[2 * g]; wa1 = wA[2 * g + 1]; }
            else       { lds_v2(aW + (g - 5) * 16384, wa0, wa1); }

            u64 p0, p1;
            lds_v2(aH + 0 * 512 + g * 16, p0, p1);
            a0r0 = fma2(wa0, p0, a0r0);  a0r0 = fma2(wa1, p1, a0r0);
            a1r0 = fma2(wb0, p0, a1r0);  a1r0 = fma2(wb1, p1, a1r0);
            lds_v2(aH + 1 * 512 + g * 16, p0, p1);
            a0r1 = fma2(wa0, p0, a0r1);  a0r1 = fma2(wa1, p1, a0r1);
            a1r1 = fma2(wb0, p0, a1r1);  a1r1 = fma2(wb1, p1, a1r1);
            lds_v2(aH + 2 * 512 + g * 16, p0, p1);
            a0r2 = fma2(wa0, p0, a0r2);  a0r2 = fma2(wa1, p1, a0r2);
            a1r2 = fma2(wb0, p0, a1r2);  a1r2 = fma2(wb1, p1, a1r2);
            lds_v2(aH + 3 * 512 + g * 16, p0, p1);
            a0r3 = fma2(wa0, p0, a0r3);  a0r3 = fma2(wa1, p1, a0r3);
            a1r3 = fma2(wb0, p0, a1r3);  a1r3 = fma2(wb1, p1, a1r3);
        }

        {
            float2 f;
            f = unpack2(a0r0); gs[(kq * 4 + 0) * 512 + c0] = f.x + f.y;
            f = unpack2(a0r1); gs[(kq * 4 + 1) * 512 + c0] = f.x + f.y;
            f = unpack2(a0r2); gs[(kq * 4 + 2) * 512 + c0] = f.x + f.y;
            f = unpack2(a0r3); gs[(kq * 4 + 3) * 512 + c0] = f.x + f.y;
            f = unpack2(a1r0); gs[(kq * 4 + 0) * 512 + c1] = f.x + f.y;
            f = unpack2(a1r1); gs[(kq * 4 + 1) * 512 + c1] = f.x + f.y;
            f = unpack2(a1r2); gs[(kq * 4 + 2) * 512 + c1] = f.x + f.y;
            f = unpack2(a1r3); gs[(kq * 4 + 3) * 512 + c1] = f.x + f.y;
        }
        __syncthreads();

        if (t < 512) {
            const float* xn = xpp + (size_t)(s + 1) * 512;
            float xn0 = __ldg(xn), xn1 = __ldg(xn + 128), xn2 = __ldg(xn + 256), xn3 = __ldg(xn + 384);

            float pi = xv0 + biasI, pf = xv1 + biasF, pg = xv2 + biasG, po = xv3 + biasO;
            #pragma unroll
            for (int q = 0; q < 4; ++q) {
                const int base = (q * 4 + br) * 512 + bj;
                pi += gs[base];
                pf += gs[base + 128];
                pg += gs[base + 256];
                po += gs[base + 384];
            }
            float ig = sigmoid_f(pi);
            float fg = sigmoid_f(pf);
            float gv = tanh_f(pg);
            float og = sigmoid_f(po);
            cval = fg * cval + ig * gv;
            hs[br * HH + bj] = og * tanh_f(cval);
            xv0 = xn0; xv1 = xn1; xv2 = xn2; xv3 = xn3;
        }
        __syncthreads();
    }

    if (t < 4) {
        float s = beff[0];
        #pragma unroll 8
        for (int j = 0; j < HH; ++j) s += hs[t * HH + j] * weff[j];
        out[r0 + t] = s;
    }
}

extern "C" void kernel_launch(void* const* d_in, const int* in_sizes, int n_in,
                              void* d_out, int out_size) {
    const float* x    = (const float*)d_in[0];
    const float* W_ih = (const float*)d_in[1];
    const float* W_hh = (const float*)d_in[2];
    const float* b_ih = (const float*)d_in[3];
    const float* b_hh = (const float*)d_in[4];
    const float* W1   = (const float*)d_in[5];
    const float* b1   = (const float*)d_in[6];
    const float* W2   = (const float*)d_in[7];
    const float* b2   = (const float*)d_in[8];
    float* out = (float*)d_out;

    cudaFuncSetAttribute(xproj_kernel,
                         cudaFuncAttributeMaxDynamicSharedMemorySize, XP_SMEM_BYTES);
    cudaFuncSetAttribute(lstm_loop_kernel,
                         cudaFuncAttributeMaxDynamicSharedMemorySize, SMEM_BYTES);

    xproj_kernel<<<4096, 512, XP_SMEM_BYTES>>>(x, W_ih);
    lstm_loop_kernel<<<NCTA, 1024, SMEM_BYTES>>>(W_hh, b_ih, b_hh, W1, b1, W2, b2, out);
}